// round 1
// baseline (speedup 1.0000x reference)
#include <cuda_runtime.h>
#include <cuda_bf16.h>
#include <math.h>

#define HW   16384
#define WDIM 128
#define NPIX (8 * 16384)

// ---------------- scratch (device globals: no allocation allowed) ----------
__device__ float g_x[8 * 64 * HW];     // fused 1x1 conv output
__device__ float g_off[8 * 18 * HW];   // raw offset conv + bias
__device__ float g_mod[8 * 9 * HW];    // 2*sigmoid(conv + bias)

// ---------------- f32x2 packed helpers ------------------------------------
__device__ __forceinline__ unsigned long long pack2(float lo, float hi) {
    unsigned long long r;
    asm("mov.b64 %0, {%1, %2};" : "=l"(r) : "f"(lo), "f"(hi));
    return r;
}
__device__ __forceinline__ void unpack2(unsigned long long v, float& lo, float& hi) {
    asm("mov.b64 {%0, %1}, %2;" : "=f"(lo), "=f"(hi) : "l"(v));
}
__device__ __forceinline__ unsigned long long fma2(unsigned long long a,
                                                   unsigned long long b,
                                                   unsigned long long c) {
    unsigned long long d;
    asm("fma.rn.f32x2 %0, %1, %2, %3;" : "=l"(d) : "l"(a), "l"(b), "l"(c));
    return d;
}

// ===========================================================================
// Kernel 1: fused 1x1 conv  x[b,o,hw] = sum_c wf[o,c] * cat(x_img,x_cont)
// ===========================================================================
__global__ void k1_fuse(const float* __restrict__ x_img,
                        const float* __restrict__ x_cont,
                        const float* __restrict__ w_fuse) {
    extern __shared__ unsigned long long s_w[];     // [128][32] u64 pairs = 32KB
    float* s_wf = (float*)s_w;                      // s_wf[c*64 + o] = wf[o*128+c]
    for (int idx = threadIdx.x; idx < 128 * 64; idx += blockDim.x) {
        int c = idx >> 6, o = idx & 63;
        s_wf[idx] = w_fuse[o * 128 + c];
    }
    __syncthreads();

    int p  = blockIdx.x * blockDim.x + threadIdx.x;
    int b  = p >> 14;
    int hw = p & 16383;
    const float* xi = x_img  + (size_t)b * 64 * HW + hw;
    const float* xc = x_cont + (size_t)b * 64 * HW + hw;

    unsigned long long acc[32];
#pragma unroll
    for (int m = 0; m < 32; m++) acc[m] = 0ULL;

#pragma unroll 1
    for (int c = 0; c < 64; c++) {
        float xv = xi[c * HW];
        unsigned long long xv2 = pack2(xv, xv);
        const unsigned long long* wrow = s_w + c * 32;
#pragma unroll
        for (int m = 0; m < 32; m += 2) {
            ulonglong2 wv = *(const ulonglong2*)(wrow + m);
            acc[m]     = fma2(wv.x, xv2, acc[m]);
            acc[m + 1] = fma2(wv.y, xv2, acc[m + 1]);
        }
    }
#pragma unroll 1
    for (int c = 0; c < 64; c++) {
        float xv = xc[c * HW];
        unsigned long long xv2 = pack2(xv, xv);
        const unsigned long long* wrow = s_w + (64 + c) * 32;
#pragma unroll
        for (int m = 0; m < 32; m += 2) {
            ulonglong2 wv = *(const ulonglong2*)(wrow + m);
            acc[m]     = fma2(wv.x, xv2, acc[m]);
            acc[m + 1] = fma2(wv.y, xv2, acc[m + 1]);
        }
    }

    float* op = g_x + (size_t)b * 64 * HW + hw;
#pragma unroll
    for (int m = 0; m < 32; m++) {
        float lo, hi;
        unpack2(acc[m], lo, hi);
        op[(2 * m) * HW]     = lo;
        op[(2 * m + 1) * HW] = hi;
    }
}

// ===========================================================================
// Kernel 2: 3x3 conv of g_x -> 18 offset channels (+bias) and 9 mod channels
//           (bias + 2*sigmoid fused)
// weights smem: s_wf[(c*9+t)*28 + j], j<18 = w_off, 18..26 = w_mod, 27 = pad
// ===========================================================================
__global__ void k2_offmod(const float* __restrict__ w_off,
                          const float* __restrict__ w_mod,
                          const float* __restrict__ b_off,
                          const float* __restrict__ b_mod) {
    extern __shared__ unsigned long long s_w[];     // 64*9*14 u64 = 63KB
    float* s_wf = (float*)s_w;
    for (int idx = threadIdx.x; idx < 64 * 9 * 28; idx += blockDim.x) {
        int c = idx / 252;
        int r = idx % 252;
        int t = r / 28;
        int j = r % 28;
        float v;
        if (j < 18)       v = w_off[((size_t)j * 64 + c) * 9 + t];
        else if (j < 27)  v = w_mod[((size_t)(j - 18) * 64 + c) * 9 + t];
        else              v = 0.0f;
        s_wf[idx] = v;
    }
    __syncthreads();

    int p  = blockIdx.x * blockDim.x + threadIdx.x;
    int b  = p >> 14;
    int hw = p & 16383;
    int h  = hw >> 7;
    int w  = hw & 127;

    unsigned long long acc[14];
#pragma unroll
    for (int m = 0; m < 14; m++) acc[m] = 0ULL;

    const float* xb0 = g_x + (size_t)b * 64 * HW;

#pragma unroll 1
    for (int c = 0; c < 64; c++) {
        const float* xb = xb0 + c * HW;
#pragma unroll
        for (int t = 0; t < 9; t++) {
            int ty = t / 3 - 1, tx = t % 3 - 1;
            int yy = h + ty, xx = w + tx;
            float xv = 0.0f;
            if ((unsigned)yy < 128u && (unsigned)xx < 128u) xv = xb[yy * 128 + xx];
            unsigned long long xv2 = pack2(xv, xv);
            const unsigned long long* wrow = s_w + (c * 9 + t) * 14;
#pragma unroll
            for (int m = 0; m < 14; m += 2) {
                ulonglong2 wv = *(const ulonglong2*)(wrow + m);
                acc[m]     = fma2(wv.x, xv2, acc[m]);
                acc[m + 1] = fma2(wv.y, xv2, acc[m + 1]);
            }
        }
    }

    float accf[28];
#pragma unroll
    for (int m = 0; m < 14; m++) unpack2(acc[m], accf[2 * m], accf[2 * m + 1]);

#pragma unroll
    for (int j = 0; j < 18; j++)
        g_off[((size_t)b * 18 + j) * HW + hw] = accf[j] + b_off[j];
#pragma unroll
    for (int j = 0; j < 9; j++) {
        float m = accf[18 + j] + b_mod[j];
        g_mod[((size_t)b * 9 + j) * HW + hw] = 2.0f / (1.0f + expf(-m));
    }
}

// ===========================================================================
// Kernel 3: deformable bilinear sample (mask+mod folded into corner weights)
//           + per-pixel GEMM out[o] = sum_{i,k} w_reg[o,i,k]*sampled[i,k]
// weights smem: s_wf[(k*64+i)*64 + o] = w_reg[o*576 + i*9 + k]   (147456 B)
// ===========================================================================
__global__ void k3_deform(const float* __restrict__ w_reg,
                          float* __restrict__ out) {
    extern __shared__ unsigned long long s_w[];     // [9][64][32] u64
    float* s_wf = (float*)s_w;
    for (int idx = threadIdx.x; idx < 9 * 64 * 64; idx += blockDim.x) {
        int o = idx & 63;
        int t = idx >> 6;
        int i = t & 63;
        int k = t >> 6;
        s_wf[idx] = w_reg[(size_t)o * 576 + i * 9 + k];
    }
    __syncthreads();

    int p  = blockIdx.x * blockDim.x + threadIdx.x;
    int b  = p >> 14;
    int hw = p & 16383;
    int h  = hw >> 7;
    int w  = hw & 127;

    const float* xb = g_x + (size_t)b * 64 * HW;
    const float* offp = g_off + (size_t)b * 18 * HW + hw;
    const float* modp = g_mod + (size_t)b * 9 * HW + hw;

    unsigned long long acc[32];
#pragma unroll
    for (int m = 0; m < 32; m++) acc[m] = 0ULL;

#pragma unroll 1
    for (int k = 0; k < 9; k++) {
        int ky = k / 3, kx = k % 3;
        float dy = offp[(2 * k) * HW];
        float dx = offp[(2 * k + 1) * HW];
        float mk = modp[k * HW];

        float py = dy + (float)(h - 1 + ky);
        float px = dx + (float)(w - 1 + kx);
        float y0f = floorf(py), x0f = floorf(px);
        float wy1 = py - y0f, wy0 = 1.0f - wy1;
        float wx1 = px - x0f, wx0 = 1.0f - wx1;
        int y0 = (int)y0f, x0 = (int)x0f;
        int y1 = y0 + 1,   x1 = x0 + 1;

        bool vy0 = (unsigned)y0 < 128u, vy1 = (unsigned)y1 < 128u;
        bool vx0 = (unsigned)x0 < 128u, vx1 = (unsigned)x1 < 128u;

        float w00 = (vy0 && vx0) ? wy0 * wx0 * mk : 0.0f;
        float w01 = (vy0 && vx1) ? wy0 * wx1 * mk : 0.0f;
        float w10 = (vy1 && vx0) ? wy1 * wx0 * mk : 0.0f;
        float w11 = (vy1 && vx1) ? wy1 * wx1 * mk : 0.0f;

        int y0c = min(max(y0, 0), 127), y1c = min(max(y1, 0), 127);
        int x0c = min(max(x0, 0), 127), x1c = min(max(x1, 0), 127);
        int a00 = y0c * 128 + x0c;
        int a01 = y0c * 128 + x1c;
        int a10 = y1c * 128 + x0c;
        int a11 = y1c * 128 + x1c;

        const unsigned long long* wk = s_w + (size_t)k * 64 * 32;

#pragma unroll 2
        for (int i = 0; i < 64; i++) {
            const float* pi = xb + i * HW;
            float s = pi[a00] * w00;
            s = fmaf(pi[a01], w01, s);
            s = fmaf(pi[a10], w10, s);
            s = fmaf(pi[a11], w11, s);
            unsigned long long s2 = pack2(s, s);
            const unsigned long long* wrow = wk + i * 32;
#pragma unroll
            for (int m = 0; m < 32; m += 2) {
                ulonglong2 wv = *(const ulonglong2*)(wrow + m);
                acc[m]     = fma2(wv.x, s2, acc[m]);
                acc[m + 1] = fma2(wv.y, s2, acc[m + 1]);
            }
        }
    }

    float* op = out + (size_t)b * 64 * HW + hw;
#pragma unroll
    for (int m = 0; m < 32; m++) {
        float lo, hi;
        unpack2(acc[m], lo, hi);
        op[(2 * m) * HW]     = lo;
        op[(2 * m + 1) * HW] = hi;
    }
}

// ===========================================================================
extern "C" void kernel_launch(void* const* d_in, const int* in_sizes, int n_in,
                              void* d_out, int out_size) {
    const float* x_img  = (const float*)d_in[0];
    const float* x_cont = (const float*)d_in[1];
    const float* w_fuse = (const float*)d_in[2];
    const float* w_off  = (const float*)d_in[3];
    const float* b_off  = (const float*)d_in[4];
    const float* w_mod  = (const float*)d_in[5];
    const float* b_mod  = (const float*)d_in[6];
    const float* w_reg  = (const float*)d_in[7];
    float* out = (float*)d_out;

    cudaFuncSetAttribute(k2_offmod,
                         cudaFuncAttributeMaxDynamicSharedMemorySize, 64 * 9 * 14 * 8);
    cudaFuncSetAttribute(k3_deform,
                         cudaFuncAttributeMaxDynamicSharedMemorySize, 9 * 64 * 32 * 8);

    const int threads = 256;
    const int blocks  = NPIX / threads;   // 512

    k1_fuse<<<blocks, threads, 128 * 32 * 8>>>(x_img, x_cont, w_fuse);
    k2_offmod<<<blocks, threads, 64 * 9 * 14 * 8>>>(w_off, w_mod, b_off, b_mod);
    k3_deform<<<blocks, threads, 9 * 64 * 32 * 8>>>(w_reg, out);
}